// round 1
// baseline (speedup 1.0000x reference)
#include <cuda_runtime.h>
#include <cuda_bf16.h>

// HistoGAN histogram loss.
// Structure: per (batch, pixel): d01 = log(r')-log(g'), d02 = log(r')-log(b'),
// d12 = log(g')-log(b'), Iy = sqrt(r'^2+g'^2+b'^2+EPS). Kernel vectors over 64
// bins; channel symmetry (delta symmetric, kernel even) means only 3 vectors
// needed. Accumulate:
//   G_AB[u,v] = sum Iy*k01[u]*k02[v]   -> hist0[u,v]        = G_AB[u,v]
//   G_AC[u,v] = sum Iy*k01[u]*k12[v]   -> hist1[u,v]        = G_AC[63-u,v]
//   G_BC[u,v] = sum Iy*k02[u]*k12[v]   -> hist2[u,v]        = G_BC[63-u,63-v]
// Then per-batch normalize and Hellinger loss vs target.

#define EPSV  (6.4f / 255.0f)
#define NPIX  65536
#define PARTS 37
#define HB    64

__device__ float g_G[8 * 3 * HB * HB];   // [B][3][64][64] scratch

// ---- packed f32x2 helpers (Blackwell) ----
__device__ __forceinline__ unsigned long long pk2(float v) {
    unsigned long long r;
    asm("mov.b64 %0, {%1, %1};" : "=l"(r) : "f"(v));
    return r;
}
__device__ __forceinline__ void fma2(unsigned long long& acc,
                                     unsigned long long a,
                                     unsigned long long b) {
    asm("fma.rn.f32x2 %0, %1, %2, %0;" : "+l"(acc) : "l"(a), "l"(b));
}
__device__ __forceinline__ float rcpa(float x) {
    float r;
    asm("rcp.approx.f32 %0, %1;" : "=f"(r) : "f"(x));
    return r;
}
__device__ __forceinline__ float lo32(unsigned long long a) {
    return __uint_as_float((unsigned)(a & 0xffffffffull));
}
__device__ __forceinline__ float hi32(unsigned long long a) {
    return __uint_as_float((unsigned)(a >> 32));
}

__global__ void zeroG_kernel(int n) {
    int i = blockIdx.x * blockDim.x + threadIdx.x;
    if (i < n) g_G[i] = 0.0f;
}

__global__ void __launch_bounds__(256, 2)
hist_accum_kernel(const float* __restrict__ rgbd) {
    __shared__ __align__(16) float sk[4][32][HB]; // vec, pixel, bin (32 KB)
    __shared__ float sdv[4][32];
    __shared__ float sw[4][32];

    const int tid  = threadIdx.x;
    const int b    = blockIdx.x / PARTS;
    const int part = blockIdx.x % PARTS;
    const int start = (int)((long long)part       * NPIX / PARTS);
    const int end   = (int)((long long)(part + 1) * NPIX / PARTS);
    const float* R = rgbd + (size_t)b * 4 * NPIX;

    // step-B mapping: thread -> (vec, bin)
    const int vecB = tid >> 6;
    const int binB = tid & 63;
    const float negd = 150.0f - (float)binB * (300.0f / 63.0f); // -delta/sigma

    // step-C mapping: thread -> 4x4 tile of each G
    const int i4 = (tid >> 4) << 2;  // u base
    const int j4 = (tid & 15) << 2;  // v base

    unsigned long long acc[3][4][2];
#pragma unroll
    for (int g = 0; g < 3; ++g)
#pragma unroll
        for (int u = 0; u < 4; ++u) {
            acc[g][u][0] = 0ull;
            acc[g][u][1] = 0ull;
        }

    for (int base = start; base < end; base += 32) {
        const int cnt = min(32, end - base);

        // ---- step A: per-pixel diffs + intensity (warp 0) ----
        if (tid < 32) {
            float d01 = 0.f, d02 = 0.f, d12 = 0.f, iy = 0.f, one = 0.f;
            if (tid < cnt) {
                const int px = base + tid;
                float r  = R[px];
                float g  = R[NPIX + px];
                float bl = R[2 * NPIX + px];
                r  = fminf(fmaxf(fmaf(r,  0.5f, 0.5f), 0.f), 1.f);
                g  = fminf(fmaxf(fmaf(g,  0.5f, 0.5f), 0.f), 1.f);
                bl = fminf(fmaxf(fmaf(bl, 0.5f, 0.5f), 0.f), 1.f);
                iy = sqrtf(fmaf(r, r, fmaf(g, g, fmaf(bl, bl, EPSV))));
                const float lr = __logf(r + EPSV);
                const float lg = __logf(g + EPSV);
                const float lb = __logf(bl + EPSV);
                d01 = lr - lg;
                d02 = lr - lb;
                d12 = lg - lb;
                one = 1.0f;
            }
            sdv[0][tid] = d01; sdv[1][tid] = d02;
            sdv[2][tid] = d12; sdv[3][tid] = d02;
            sw[0][tid] = iy;  sw[1][tid] = one;
            sw[2][tid] = one; sw[3][tid] = iy;
        }
        __syncthreads();

        // ---- step B: kernel vectors into SMEM ----
        // vec0 = Iy*k(d01), vec1 = k(d02), vec2 = k(d12), vec3 = Iy*k(d02)
#pragma unroll 8
        for (int p = 0; p < 32; ++p) {
            const float d = sdv[vecB][p];
            const float w = sw[vecB][p];
            const float q   = fmaf(d, 50.0f, negd);
            const float den = fmaf(q, q, 1.0f);
            sk[vecB][p][binB] = w * rcpa(den);
        }
        __syncthreads();

        // ---- step C: rank-1 accumulation, packed f32x2 FMAs ----
#pragma unroll 4
        for (int p = 0; p < 32; ++p) {
            const float4 u0 = *(const float4*)&sk[0][p][i4];       // Iy*k01
            const float4 u3 = *(const float4*)&sk[3][p][i4];       // Iy*k02
            const ulonglong2 v1 = *(const ulonglong2*)&sk[1][p][j4]; // k02
            const ulonglong2 v2 = *(const ulonglong2*)&sk[2][p][j4]; // k12
            unsigned long long a;

            a = pk2(u0.x);
            fma2(acc[0][0][0], a, v1.x); fma2(acc[0][0][1], a, v1.y);
            fma2(acc[1][0][0], a, v2.x); fma2(acc[1][0][1], a, v2.y);
            a = pk2(u0.y);
            fma2(acc[0][1][0], a, v1.x); fma2(acc[0][1][1], a, v1.y);
            fma2(acc[1][1][0], a, v2.x); fma2(acc[1][1][1], a, v2.y);
            a = pk2(u0.z);
            fma2(acc[0][2][0], a, v1.x); fma2(acc[0][2][1], a, v1.y);
            fma2(acc[1][2][0], a, v2.x); fma2(acc[1][2][1], a, v2.y);
            a = pk2(u0.w);
            fma2(acc[0][3][0], a, v1.x); fma2(acc[0][3][1], a, v1.y);
            fma2(acc[1][3][0], a, v2.x); fma2(acc[1][3][1], a, v2.y);

            a = pk2(u3.x);
            fma2(acc[2][0][0], a, v2.x); fma2(acc[2][0][1], a, v2.y);
            a = pk2(u3.y);
            fma2(acc[2][1][0], a, v2.x); fma2(acc[2][1][1], a, v2.y);
            a = pk2(u3.z);
            fma2(acc[2][2][0], a, v2.x); fma2(acc[2][2][1], a, v2.y);
            a = pk2(u3.w);
            fma2(acc[2][3][0], a, v2.x); fma2(acc[2][3][1], a, v2.y);
        }
        __syncthreads();
    }

    // ---- flush partial G to global ----
    float* Gb = g_G + (size_t)b * 3 * HB * HB;
#pragma unroll
    for (int g = 0; g < 3; ++g)
#pragma unroll
        for (int u = 0; u < 4; ++u)
#pragma unroll
            for (int pr = 0; pr < 2; ++pr) {
                const unsigned long long a = acc[g][u][pr];
                const int row = i4 + u;
                const int col = j4 + pr * 2;
                atomicAdd(&Gb[g * HB * HB + row * HB + col],     lo32(a));
                atomicAdd(&Gb[g * HB * HB + row * HB + col + 1], hi32(a));
            }
}

// block reduce over 1024 threads (32 warps)
__device__ __forceinline__ float block_reduce(float v, float* sh) {
#pragma unroll
    for (int o = 16; o > 0; o >>= 1)
        v += __shfl_xor_sync(0xffffffffu, v, o);
    const int lane = threadIdx.x & 31;
    const int w    = threadIdx.x >> 5;
    __syncthreads();           // protect sh reuse across calls
    if (lane == 0) sh[w] = v;
    __syncthreads();
    if (w == 0) {
        v = sh[lane];
#pragma unroll
        for (int o = 16; o > 0; o >>= 1)
            v += __shfl_xor_sync(0xffffffffu, v, o);
    }
    return v;   // valid on thread 0
}

__global__ void loss_kernel(const float* __restrict__ th,
                            float* __restrict__ out, int B) {
    __shared__ float sh[32];
    __shared__ float sinv[8];
    const int tid = threadIdx.x;

    // per-batch normalization (sums are flip-invariant)
    for (int b = 0; b < B; ++b) {
        float s = 0.f;
        for (int k = tid; k < 3 * HB * HB; k += 1024)
            s += g_G[b * 3 * HB * HB + k];
        s = block_reduce(s, sh);
        if (tid == 0) sinv[b] = 1.0f / (s + EPSV);
    }
    __syncthreads();

    // Hellinger accumulation with flip mapping
    float acc = 0.f;
    const int total = B * 3 * HB * HB;
    for (int idx = tid; idx < total; idx += 1024) {
        const int b = idx / (3 * HB * HB);
        const int r = idx - b * (3 * HB * HB);
        const int c = r >> 12;
        const int q = r & 4095;
        const int u = q >> 6;
        const int v = q & 63;
        const float* Gb = g_G + b * 3 * HB * HB;
        float h;
        if (c == 0)      h = Gb[q];
        else if (c == 1) h = Gb[4096 + ((63 - u) << 6) + v];
        else             h = Gb[8192 + ((63 - u) << 6) + (63 - v)];
        h *= sinv[b];
        const float d = sqrtf(th[r]) - sqrtf(h);
        acc = fmaf(d, d, acc);
    }
    acc = block_reduce(acc, sh);
    if (tid == 0)
        out[0] = sqrtf(acc) * (0.70710678118654752f / (float)B);
}

extern "C" void kernel_launch(void* const* d_in, const int* in_sizes, int n_in,
                              void* d_out, int out_size) {
    const float* rgbd = (const float*)d_in[0];
    const float* th   = (const float*)d_in[1];
    float* out        = (float*)d_out;

    const int B = in_sizes[0] / (4 * NPIX);   // 8
    const int nG = B * 3 * HB * HB;

    zeroG_kernel<<<(nG + 1023) / 1024, 1024>>>(nG);
    hist_accum_kernel<<<B * PARTS, 256>>>(rgbd);
    loss_kernel<<<1, 1024>>>(th, out, B);
}

// round 3
// speedup vs baseline: 1.7538x; 1.7538x over previous
#include <cuda_runtime.h>
#include <cstdint>

// HistoGAN histogram loss via mma.sync tf32 (register accumulators; no TMEM —
// tcgen05.ld is sm_103a-only and this toolchain emits family sm_103 PTX).
//
// Per pixel: d01,d02,d12 (log-chroma diffs), Iy. Kernel vectors over 64 bins.
// A-stack (128 rows, K=pixels): rows 0-63 = Iy*k01, rows 64-127 = Iy*k02
// B0 (64 cols) = k02, B1 (64 cols) = k12.
//   G_AB = Atop x B0, G_AC = Atop x B1, G_BC = Abot x B1
// hist0[u,v]=G_AB[u,v]; hist1[u,v]=G_AC[63-u,v]; hist2[u,v]=G_BC[63-u,63-v]

#define EPSV  (6.4f / 255.0f)
#define NPIX  65536
#define PARTS 37
#define QSTEP 4.76190476190476f   /* 300/63 */
#define LDA   136                 /* 128 + 8 : ≡8 mod 32 -> conflict-free frags */
#define LDB   72                  /* 64 + 8  */

__device__ float g_G[8 * 3 * 64 * 64];   // [B][3][64][64] raw (flips at loss)

static __device__ __forceinline__ float rcpa(float x) {
    float r; asm("rcp.approx.f32 %0, %1;" : "=f"(r) : "f"(x)); return r;
}

static __device__ __forceinline__ void mma8(float* c,
        uint32_t a0, uint32_t a1, uint32_t a2, uint32_t a3,
        uint32_t b0, uint32_t b1) {
    asm("mma.sync.aligned.m16n8k8.row.col.f32.tf32.tf32.f32 "
        "{%0,%1,%2,%3},{%4,%5,%6,%7},{%8,%9},{%0,%1,%2,%3};"
        : "+f"(c[0]), "+f"(c[1]), "+f"(c[2]), "+f"(c[3])
        : "r"(a0), "r"(a1), "r"(a2), "r"(a3), "r"(b0), "r"(b1));
}

__global__ void __launch_bounds__(256, 2)
hist_kernel(const float* __restrict__ rgbd) {
    __shared__ __align__(16) float  sA [32 * LDA];   // [k][row0..127]
    __shared__ __align__(16) float  sB0[32 * LDB];   // [k][col0..63]  k02
    __shared__ __align__(16) float  sB1[32 * LDB];   // [k][col0..63]  k12
    __shared__ __align__(16) float4 spix[32];        // (d01,d02,d12,Iy)

    const int tid  = threadIdx.x;
    const int lane = tid & 31;
    const int w    = tid >> 5;
    const int b    = blockIdx.x / PARTS;
    const int part = blockIdx.x % PARTS;
    const int start = (int)((long long)part       * NPIX / PARTS);
    const int end   = (int)((long long)(part + 1) * NPIX / PARTS);
    const float* R = rgbd + (size_t)b * 4 * NPIX;

    // producer mapping: group = tid>>6 (0..3), bin = tid&63
    const int   grp  = tid >> 6;
    const int   binq = tid & 63;
    const float negd = 150.0f - (float)binq * QSTEP;   // -delta/sigma

    // consumer mapping
    const int kc  = lane & 3;    // k within 4
    const int ln4 = lane >> 2;   // row/col within 8

    float acc[12][4];
#pragma unroll
    for (int t = 0; t < 12; ++t) { acc[t][0]=0.f; acc[t][1]=0.f; acc[t][2]=0.f; acc[t][3]=0.f; }

    const uint32_t* Au  = (const uint32_t*)sA;
    const uint32_t* B0u = (const uint32_t*)sB0;
    const uint32_t* B1u = (const uint32_t*)sB1;

    const int nch = (end - start + 31) >> 5;
    for (int c = 0; c < nch; ++c) {
        const int base = start + (c << 5);

        __syncthreads();   // prev consume done; safe to rewrite SMEM
        if (tid < 32) {
            float4 P = make_float4(0.f, 0.f, 0.f, 0.f);
            const int px = base + tid;
            if (px < end) {
                float r  = fminf(fmaxf(fmaf(R[px],            0.5f, 0.5f), 0.f), 1.f);
                float g  = fminf(fmaxf(fmaf(R[NPIX + px],     0.5f, 0.5f), 0.f), 1.f);
                float bl = fminf(fmaxf(fmaf(R[2 * NPIX + px], 0.5f, 0.5f), 0.f), 1.f);
                const float iy = sqrtf(fmaf(r, r, fmaf(g, g, fmaf(bl, bl, EPSV))));
                const float lr = __logf(r + EPSV);
                const float lg = __logf(g + EPSV);
                const float lb = __logf(bl + EPSV);
                P = make_float4(lr - lg, lr - lb, lg - lb, iy);
            }
            spix[tid] = P;
        }
        __syncthreads();

        // ---- producers: fill operand tiles (all STS conflict-free) ----
        if (grp == 0) {            // A rows 0-63: Iy*k01
#pragma unroll 8
            for (int p = 0; p < 32; ++p) {
                const float4 P = spix[p];
                const float q = fmaf(P.x, 50.f, negd);
                sA[p * LDA + binq] = P.w * rcpa(fmaf(q, q, 1.f));
            }
        } else if (grp == 1) {     // A rows 64-127: Iy*k02
#pragma unroll 8
            for (int p = 0; p < 32; ++p) {
                const float4 P = spix[p];
                const float q = fmaf(P.y, 50.f, negd);
                sA[p * LDA + 64 + binq] = P.w * rcpa(fmaf(q, q, 1.f));
            }
        } else if (grp == 2) {     // B0: k02
#pragma unroll 8
            for (int p = 0; p < 32; ++p) {
                const float4 P = spix[p];
                const float q = fmaf(P.y, 50.f, negd);
                sB0[p * LDB + binq] = rcpa(fmaf(q, q, 1.f));
            }
        } else {                   // B1: k12
#pragma unroll 8
            for (int p = 0; p < 32; ++p) {
                const float4 P = spix[p];
                const float q = fmaf(P.z, 50.f, negd);
                sB1[p * LDB + binq] = rcpa(fmaf(q, q, 1.f));
            }
        }
        __syncthreads();

        // ---- consumers: 96 m16n8k8 tiles across 8 warps ----
        if (w < 4) {
            // slab w (A rows 16w..16w+15) x coltiles 0-11 (B0 0-7, B1 0-3)
            const int rowA = 16 * w + ln4;
#pragma unroll
            for (int ks = 0; ks < 4; ++ks) {
                const int ab = (8 * ks + kc) * LDA + rowA;
                const uint32_t a0 = Au[ab],           a1 = Au[ab + 8];
                const uint32_t a2 = Au[ab + 4 * LDA], a3 = Au[ab + 4 * LDA + 8];
                const int bb = (8 * ks + kc) * LDB + ln4;
#pragma unroll
                for (int t = 0; t < 8; ++t) {
                    const uint32_t b0 = B0u[bb + 8 * t];
                    const uint32_t b1 = B0u[bb + 8 * t + 4 * LDB];
                    mma8(acc[t], a0, a1, a2, a3, b0, b1);
                }
#pragma unroll
                for (int t = 0; t < 4; ++t) {
                    const uint32_t b0 = B1u[bb + 8 * t];
                    const uint32_t b1 = B1u[bb + 8 * t + 4 * LDB];
                    mma8(acc[8 + t], a0, a1, a2, a3, b0, b1);
                }
            }
        } else {
            // bottom slab (A rows 64+16(w-4)..) x B1 cols 0-63 (8 tiles)
            // + top slab (w-4) x B1 cols 32-63 (4 tiles, shared B frags)
            const int rowT = 16 * (w - 4) + ln4;
            const int rowB = 64 + 16 * (w - 4) + ln4;
#pragma unroll
            for (int ks = 0; ks < 4; ++ks) {
                const int abT = (8 * ks + kc) * LDA + rowT;
                const int abB = (8 * ks + kc) * LDA + rowB;
                const uint32_t t0 = Au[abT],           t1 = Au[abT + 8];
                const uint32_t t2 = Au[abT + 4 * LDA], t3 = Au[abT + 4 * LDA + 8];
                const uint32_t u0 = Au[abB],           u1 = Au[abB + 8];
                const uint32_t u2 = Au[abB + 4 * LDA], u3 = Au[abB + 4 * LDA + 8];
                const int bb = (8 * ks + kc) * LDB + ln4;
#pragma unroll
                for (int j = 0; j < 8; ++j) {
                    const uint32_t b0 = B1u[bb + 8 * j];
                    const uint32_t b1 = B1u[bb + 8 * j + 4 * LDB];
                    mma8(acc[j], u0, u1, u2, u3, b0, b1);       // G_BC
                    if (j >= 4)
                        mma8(acc[8 + j - 4], t0, t1, t2, t3, b0, b1);  // G_AC v=32..63
                }
            }
        }
    }

    // ---- epilogue: register tiles -> g_G via atomics ----
    float* Gb = g_G + (size_t)b * 3 * 4096;
    const int cuv = 2 * (lane & 3);
    if (w < 4) {
        const int u0 = 16 * w + ln4;
#pragma unroll
        for (int t = 0; t < 12; ++t) {
            const int mat = (t < 8) ? 0 : 1;
            const int v   = ((t < 8) ? 8 * t : 8 * (t - 8)) + cuv;
            float* p0 = Gb + mat * 4096 + u0 * 64 + v;
            atomicAdd(p0,            acc[t][0]);
            atomicAdd(p0 + 1,        acc[t][1]);
            atomicAdd(p0 + 8 * 64,     acc[t][2]);
            atomicAdd(p0 + 8 * 64 + 1, acc[t][3]);
        }
    } else {
        const int u0 = 16 * (w - 4) + ln4;
#pragma unroll
        for (int j = 0; j < 8; ++j) {           // G_BC (mat 2)
            float* p0 = Gb + 2 * 4096 + u0 * 64 + 8 * j + cuv;
            atomicAdd(p0,            acc[j][0]);
            atomicAdd(p0 + 1,        acc[j][1]);
            atomicAdd(p0 + 8 * 64,     acc[j][2]);
            atomicAdd(p0 + 8 * 64 + 1, acc[j][3]);
        }
#pragma unroll
        for (int i = 0; i < 4; ++i) {           // G_AC v=32..63 (mat 1)
            float* p0 = Gb + 1 * 4096 + u0 * 64 + 8 * (4 + i) + cuv;
            atomicAdd(p0,            acc[8 + i][0]);
            atomicAdd(p0 + 1,        acc[8 + i][1]);
            atomicAdd(p0 + 8 * 64,     acc[8 + i][2]);
            atomicAdd(p0 + 8 * 64 + 1, acc[8 + i][3]);
        }
    }
}

// ---------------- loss kernel (reads + re-zeroes g_G for graph replay) -------
static __device__ __forceinline__ float block_reduce(float v, float* sh) {
#pragma unroll
    for (int o = 16; o > 0; o >>= 1) v += __shfl_xor_sync(0xffffffffu, v, o);
    const int lane = threadIdx.x & 31;
    const int w    = threadIdx.x >> 5;
    __syncthreads();
    if (lane == 0) sh[w] = v;
    __syncthreads();
    if (w == 0) {
        v = sh[lane];
#pragma unroll
        for (int o = 16; o > 0; o >>= 1) v += __shfl_xor_sync(0xffffffffu, v, o);
    }
    return v;   // valid on thread 0
}

__global__ void loss_kernel(const float* __restrict__ th,
                            float* __restrict__ out, int B) {
    __shared__ float sh[32];
    __shared__ float sinv[8];
    const int tid = threadIdx.x;

    for (int b = 0; b < B; ++b) {
        float s = 0.f;
        for (int k = tid; k < 3 * 4096; k += 1024)
            s += g_G[b * 3 * 4096 + k];
        s = block_reduce(s, sh);
        if (tid == 0) sinv[b] = 1.0f / (s + EPSV);
    }
    __syncthreads();

    float acc = 0.f;
    const int total = B * 3 * 4096;
    for (int idx = tid; idx < total; idx += 1024) {
        const int b = idx / (3 * 4096);
        const int r = idx - b * (3 * 4096);
        const int c = r >> 12;
        const int q = r & 4095;
        const int u = q >> 6;
        const int v = q & 63;
        float* Gb = g_G + b * 3 * 4096;
        int addr;
        if (c == 0)      addr = q;
        else if (c == 1) addr = 4096 + ((63 - u) << 6) + v;
        else             addr = 8192 + ((63 - u) << 6) + (63 - v);
        const float h = Gb[addr] * sinv[b];
        Gb[addr] = 0.0f;                 // reset for next replay
        const float d = sqrtf(th[r]) - sqrtf(h);
        acc = fmaf(d, d, acc);
    }
    acc = block_reduce(acc, sh);
    if (tid == 0)
        out[0] = sqrtf(acc) * (0.70710678118654752f / (float)B);
}

extern "C" void kernel_launch(void* const* d_in, const int* in_sizes, int n_in,
                              void* d_out, int out_size) {
    const float* rgbd = (const float*)d_in[0];
    const float* th   = (const float*)d_in[1];
    float* out        = (float*)d_out;

    const int B = in_sizes[0] / (4 * NPIX);   // 8

    hist_kernel<<<B * PARTS, 256>>>(rgbd);
    loss_kernel<<<1, 1024>>>(th, out, B);
}

// round 4
// speedup vs baseline: 3.1000x; 1.7675x over previous
#include <cuda_runtime.h>
#include <cuda_fp16.h>
#include <cstdint>

// HistoGAN histogram loss via mma.sync f16 (register accumulators).
// A-stack (128 rows, K=px): rows 0-63 = Iy*k01, rows 64-127 = Iy*k02
// B0 = k02 (64 cols), B1 = k12 (64 cols).
//   G_AB = Atop x B0, G_AC = Atop x B1, G_BC = Abot x B1
// hist0[u,v]=G_AB[u,v]; hist1[u,v]=G_AC[63-u,v]; hist2[u,v]=G_BC[63-u,63-v]
// Operand SMEM is k-major packed half2 pairs: s[kpair][row], conflict-free
// for both producer STS and mma fragment LDS.

#define EPSV  (6.4f / 255.0f)
#define NPIX  65536
#define PARTS 37
#define QSTEP 4.761904761904762f   /* 300/63 */
#define LDA   136                  /* words per kpair row of A (128 + 8) */
#define LDB   72                   /* words per kpair row of B (64 + 8)  */

__device__ float g_G[8 * 3 * 4096];   // [B][3][64][64] raw
__device__ float g_sum[8];            // per-batch total mass
__device__ float g_acc;               // Hellinger sum accumulator

static __device__ __forceinline__ float rcpa(float x) {
    float r; asm("rcp.approx.f32 %0, %1;" : "=f"(r) : "f"(x)); return r;
}
static __device__ __forceinline__ uint32_t packh2(float lo, float hi) {
    __half2 h = __floats2half2_rn(lo, hi);
    return *(uint32_t*)&h;
}
static __device__ __forceinline__ void mma16(float* c,
        uint32_t a0, uint32_t a1, uint32_t a2, uint32_t a3,
        uint32_t b0, uint32_t b1) {
    asm("mma.sync.aligned.m16n8k16.row.col.f32.f16.f16.f32 "
        "{%0,%1,%2,%3},{%4,%5,%6,%7},{%8,%9},{%0,%1,%2,%3};"
        : "+f"(c[0]), "+f"(c[1]), "+f"(c[2]), "+f"(c[3])
        : "r"(a0), "r"(a1), "r"(a2), "r"(a3), "r"(b0), "r"(b1));
}

__global__ void __launch_bounds__(192, 2)
hist_kernel(const float* __restrict__ rgbd) {
    __shared__ __align__(16) uint32_t sA [16 * LDA];   // [kpair][row 0..127]
    __shared__ __align__(16) uint32_t sB0[16 * LDB];   // [kpair][col 0..63] k02
    __shared__ __align__(16) uint32_t sB1[16 * LDB];   // [kpair][col 0..63] k12
    __shared__ __align__(16) float4   spix[2][32];     // (d01,d02,d12,Iy) x2 buf

    const int tid  = threadIdx.x;
    const int lane = tid & 31;
    const int w    = tid >> 5;
    const int b    = blockIdx.x / PARTS;
    const int part = blockIdx.x % PARTS;
    const int start = (int)((long long)part       * NPIX / PARTS);
    const int end   = (int)((long long)(part + 1) * NPIX / PARTS);
    const float* R  = rgbd + (size_t)b * 4 * NPIX;

    // producer mapping: vec 0..2, px-pair 0..15, bin = t2 + 4j
    const int   vec = tid >> 6;
    const int   sub = tid & 63;
    const int   p2  = sub >> 2;
    const int   t2  = sub & 3;
    const float negd0 = 150.0f - (float)t2 * QSTEP;

    // mma mapping: 6 warps, each 32 rows x 64 cols of one matrix
    const int m  = w >> 1;                 // 0=AB, 1=AC, 2=BC
    const int rh = w & 1;
    const int kc  = lane & 3;
    const int ln4 = lane >> 2;
    const int rowbase = ((m == 2) ? 64 : 0) + 32 * rh + ln4;
    const uint32_t* Bsel = (m == 0) ? sB0 : sB1;

    float acc[2][8][4];
#pragma unroll
    for (int s = 0; s < 2; ++s)
#pragma unroll
        for (int t = 0; t < 8; ++t)
#pragma unroll
            for (int i = 0; i < 4; ++i) acc[s][t][i] = 0.f;

    // pixel prep for chunk 0
    if (w == 0) {
        float4 P = make_float4(0.f, 0.f, 0.f, 0.f);
        const int px = start + lane;
        if (px < end) {
            float r  = fminf(fmaxf(fmaf(R[px],            0.5f, 0.5f), 0.f), 1.f);
            float g  = fminf(fmaxf(fmaf(R[NPIX + px],     0.5f, 0.5f), 0.f), 1.f);
            float bl = fminf(fmaxf(fmaf(R[2 * NPIX + px], 0.5f, 0.5f), 0.f), 1.f);
            float iy = sqrtf(fmaf(r, r, fmaf(g, g, fmaf(bl, bl, EPSV))));
            float lr = __logf(r + EPSV), lg = __logf(g + EPSV), lb = __logf(bl + EPSV);
            P = make_float4(lr - lg, lr - lb, lg - lb, iy);
        }
        spix[0][lane] = P;
    }
    __syncthreads();

    const int nch = (end - start + 31) >> 5;
    for (int c = 0; c < nch; ++c) {
        const int buf = c & 1;

        // prefetch next chunk's pixels (LDG latency hidden by produce phase)
        float rr = 0.f, gg = 0.f, bb = 0.f;
        bool val = false;
        if (w == 0) {
            const int px = start + (c + 1) * 32 + lane;
            if (px < end) {
                val = true;
                rr = R[px]; gg = R[NPIX + px]; bb = R[2 * NPIX + px];
            }
        }

        // ---- produce operand tiles from spix[buf] ----
        {
            const float4 Pa = spix[buf][2 * p2];
            const float4 Pb = spix[buf][2 * p2 + 1];
            const float da = (vec == 0) ? Pa.x : ((vec == 1) ? Pa.y : Pa.z);
            const float db = (vec == 0) ? Pb.x : ((vec == 1) ? Pb.y : Pb.z);
            const float ia = Pa.w, ib = Pb.w;
#pragma unroll
            for (int j = 0; j < 16; ++j) {
                const float negd = negd0 - (float)(4 * j) * QSTEP;
                const float qa = fmaf(da, 50.f, negd);
                const float qb = fmaf(db, 50.f, negd);
                const float ka = rcpa(fmaf(qa, qa, 1.f));
                const float kb = rcpa(fmaf(qb, qb, 1.f));
                const int bin = t2 + 4 * j;
                if (vec == 0) {
                    sA[p2 * LDA + bin] = packh2(ia * ka, ib * kb);
                } else if (vec == 1) {
                    sB0[p2 * LDB + bin]      = packh2(ka, kb);
                    sA [p2 * LDA + 64 + bin] = packh2(ia * ka, ib * kb);
                } else {
                    sB1[p2 * LDB + bin] = packh2(ka, kb);
                }
            }
        }

        // store prefetched pixel data into the other spix buffer
        if (w == 0) {
            float4 P = make_float4(0.f, 0.f, 0.f, 0.f);
            if (val) {
                float r  = fminf(fmaxf(fmaf(rr, 0.5f, 0.5f), 0.f), 1.f);
                float g  = fminf(fmaxf(fmaf(gg, 0.5f, 0.5f), 0.f), 1.f);
                float bl = fminf(fmaxf(fmaf(bb, 0.5f, 0.5f), 0.f), 1.f);
                float iy = sqrtf(fmaf(r, r, fmaf(g, g, fmaf(bl, bl, EPSV))));
                float lr = __logf(r + EPSV), lg = __logf(g + EPSV), lb = __logf(bl + EPSV);
                P = make_float4(lr - lg, lr - lb, lg - lb, iy);
            }
            spix[buf ^ 1][lane] = P;
        }
        __syncthreads();

        // ---- MMA: 2 k16 steps, 16 tiles per warp ----
#pragma unroll
        for (int ks = 0; ks < 2; ++ks) {
            const int k0 = (ks * 8 + kc) * LDA + rowbase;
            const int k1 = (ks * 8 + kc + 4) * LDA + rowbase;
            const uint32_t a00 = sA[k0],      a01 = sA[k0 + 8];
            const uint32_t a02 = sA[k1],      a03 = sA[k1 + 8];
            const uint32_t a10 = sA[k0 + 16], a11 = sA[k0 + 24];
            const uint32_t a12 = sA[k1 + 16], a13 = sA[k1 + 24];
            const int bb0 = (ks * 8 + kc) * LDB + ln4;
            const int bb1 = (ks * 8 + kc + 4) * LDB + ln4;
#pragma unroll
            for (int t = 0; t < 8; ++t) {
                const uint32_t b0 = Bsel[bb0 + 8 * t];
                const uint32_t b1 = Bsel[bb1 + 8 * t];
                mma16(acc[0][t], a00, a01, a02, a03, b0, b1);
                mma16(acc[1][t], a10, a11, a12, a13, b0, b1);
            }
        }
        __syncthreads();   // MMA done reading before next produce overwrites
    }

    // ---- per-batch mass (normalization) folded into epilogue ----
    float lsum = 0.f;
#pragma unroll
    for (int s = 0; s < 2; ++s)
#pragma unroll
        for (int t = 0; t < 8; ++t)
#pragma unroll
            for (int i = 0; i < 4; ++i) lsum += acc[s][t][i];
#pragma unroll
    for (int o = 16; o > 0; o >>= 1) lsum += __shfl_xor_sync(~0u, lsum, o);
    if (lane == 0) atomicAdd(&g_sum[b], lsum);

    // ---- flush partial G ----
    float* Gm = g_G + (size_t)b * 3 * 4096 + m * 4096;
    const int urow = 32 * rh + ln4;
    const int col  = 2 * (lane & 3);
#pragma unroll
    for (int s = 0; s < 2; ++s) {
#pragma unroll
        for (int t = 0; t < 8; ++t) {
            float* p0 = Gm + (urow + 16 * s) * 64 + 8 * t + col;
            atomicAdd(p0,              acc[s][t][0]);
            atomicAdd(p0 + 1,          acc[s][t][1]);
            atomicAdd(p0 + 8 * 64,     acc[s][t][2]);
            atomicAdd(p0 + 8 * 64 + 1, acc[s][t][3]);
        }
    }
}

// ---- Hellinger partial sums: 24 CTAs (batch x matrix); also re-zero g_G ----
__global__ void hell_kernel(const float* __restrict__ th) {
    __shared__ float sh[8];
    const int bc = blockIdx.x;
    const int b  = bc / 3, c = bc % 3;
    const float inv = 1.0f / (g_sum[b] + EPSV);
    float* Gb = g_G + (size_t)b * 3 * 4096 + c * 4096;

    float a = 0.f;
    for (int i = threadIdx.x; i < 4096; i += 256) {
        const int u = i >> 6, v = i & 63;
        int addr;
        if (c == 0)      addr = i;
        else if (c == 1) addr = ((63 - u) << 6) + v;
        else             addr = ((63 - u) << 6) + (63 - v);
        const float h = Gb[addr] * inv;
        Gb[addr] = 0.f;                       // reset for next graph replay
        const float d = sqrtf(th[c * 4096 + i]) - sqrtf(h);
        a = fmaf(d, d, a);
    }
#pragma unroll
    for (int o = 16; o > 0; o >>= 1) a += __shfl_xor_sync(~0u, a, o);
    if ((threadIdx.x & 31) == 0) sh[threadIdx.x >> 5] = a;
    __syncthreads();
    if (threadIdx.x == 0) {
        float s = 0.f;
#pragma unroll
        for (int i = 0; i < 8; ++i) s += sh[i];
        atomicAdd(&g_acc, s);
    }
}

__global__ void final_kernel(float* __restrict__ out, int B) {
    out[0] = sqrtf(g_acc) * (0.70710678118654752f / (float)B);
    g_acc = 0.f;
#pragma unroll
    for (int i = 0; i < 8; ++i) g_sum[i] = 0.f;
}

extern "C" void kernel_launch(void* const* d_in, const int* in_sizes, int n_in,
                              void* d_out, int out_size) {
    const float* rgbd = (const float*)d_in[0];
    const float* th   = (const float*)d_in[1];
    float* out        = (float*)d_out;

    const int B = in_sizes[0] / (4 * NPIX);   // 8

    hist_kernel<<<B * PARTS, 192>>>(rgbd);
    hell_kernel<<<B * 3, 256>>>(th);
    final_kernel<<<1, 1>>>(out, B);
}

// round 5
// speedup vs baseline: 3.5734x; 1.1527x over previous
#include <cuda_runtime.h>
#include <cuda_fp16.h>
#include <cstdint>

// HistoGAN histogram loss via mma.sync f16, KC=64, double-buffered operands,
// one sync per chunk, f16x2 reciprocal for kernel evaluation.
//
// A-stack (128 rows, K=px): rows 0-63 = Iy*k01, rows 64-127 = Iy*k02
// B0 = k02 (64 cols), B1 = k12 (64 cols).
//   G_AB = Atop x B0, G_AC = Atop x B1, G_BC = Abot x B1
// hist0[u,v]=G_AB[u,v]; hist1[u,v]=G_AC[63-u,v]; hist2[u,v]=G_BC[63-u,63-v]

#define EPSV  (6.4f / 255.0f)
#define NPIX  65536
#define PARTS 37
#define QSTEP 4.761904761904762f   /* 300/63 */
#define KC    64
#define LDA   136                  /* half2 words per kpair row of A (128+8) */
#define LDB   72                   /* half2 words per kpair row of B (64+8)  */
#define AW    (32 * LDA)           /* 4352 words */
#define BW    (32 * LDB)           /* 2304 words */
#define STAGEW (AW + 2 * BW)       /* 8960 words per stage */
#define DSMEMB (2 * STAGEW * 4)    /* 71680 bytes */

__device__ float g_G[8 * 3 * 4096];   // [B][3][64][64] raw
__device__ float g_sum[8];            // per-batch total mass
__device__ float g_acc;               // Hellinger sum accumulator

static __device__ __forceinline__ void mma16(float* c,
        uint32_t a0, uint32_t a1, uint32_t a2, uint32_t a3,
        uint32_t b0, uint32_t b1) {
    asm("mma.sync.aligned.m16n8k16.row.col.f32.f16.f16.f32 "
        "{%0,%1,%2,%3},{%4,%5,%6,%7},{%8,%9},{%0,%1,%2,%3};"
        : "+f"(c[0]), "+f"(c[1]), "+f"(c[2]), "+f"(c[3])
        : "r"(a0), "r"(a1), "r"(a2), "r"(a3), "r"(b0), "r"(b1));
}

static __device__ __forceinline__ float4 pix_math(float rr, float gg, float bb) {
    float r  = fminf(fmaxf(fmaf(rr, 0.5f, 0.5f), 0.f), 1.f);
    float g  = fminf(fmaxf(fmaf(gg, 0.5f, 0.5f), 0.f), 1.f);
    float bl = fminf(fmaxf(fmaf(bb, 0.5f, 0.5f), 0.f), 1.f);
    float iy = sqrtf(fmaf(r, r, fmaf(g, g, fmaf(bl, bl, EPSV))));
    float lr = __logf(r + EPSV), lg = __logf(g + EPSV), lb = __logf(bl + EPSV);
    return make_float4(lr - lg, lr - lb, lg - lb, iy);
}

__global__ void __launch_bounds__(192, 2)
hist_kernel(const float* __restrict__ rgbd) {
    extern __shared__ uint32_t sm[];                 // 2 operand stages
    __shared__ __align__(16) float4 spix[2][KC];     // pixel params, 2 buffers

    const int tid  = threadIdx.x;
    const int lane = tid & 31;
    const int w    = tid >> 5;
    const int b    = blockIdx.x / PARTS;
    const int part = blockIdx.x % PARTS;
    const int start = (int)((long long)part       * NPIX / PARTS);
    const int end   = (int)((long long)(part + 1) * NPIX / PARTS);
    const float* R  = rgbd + (size_t)b * 4 * NPIX;

    // producer mapping: vec = tid/64 (0:k01A, 1:k02->B0+A64, 2:k12->B1)
    const int vec = tid >> 6;
    const int sub = tid & 63;
    const int p2  = sub >> 2;          // pair base 0..15 (pairs p2, p2+16)
    const int t2  = sub & 3;
    const int rot = p2 >> 2;           // bank-derotation 0..3

    // consumer mapping: 6 warps x (32 rows x 64 cols)
    const int m   = w >> 1;            // 0=AB, 1=AC, 2=BC
    const int rh  = w & 1;
    const int kc  = lane & 3;
    const int ln4 = lane >> 2;
    const int rowbase = ((m == 2) ? 64 : 0) + 32 * rh + ln4;

    float acc[2][8][4];
#pragma unroll
    for (int s = 0; s < 2; ++s)
#pragma unroll
        for (int t = 0; t < 8; ++t)
#pragma unroll
            for (int i = 0; i < 4; ++i) acc[s][t][i] = 0.f;

    const int nch = (end - start + KC - 1) / KC;

    // prep pixels for chunk 0 (vec-2 threads: tid 128..191)
    if (tid >= 128) {
        const int q = tid - 128;
        const int px = start + q;
        float4 P = make_float4(0.f, 0.f, 0.f, 0.f);
        if (px < end) P = pix_math(R[px], R[NPIX + px], R[2 * NPIX + px]);
        spix[0][q] = P;
    }
    __syncthreads();

    for (int c = 0; c < nch; ++c) {
        const int buf = c & 1;
        uint32_t* A  = sm + buf * STAGEW;
        uint32_t* B0 = A + AW;
        uint32_t* B1 = B0 + BW;

        // early LDG for next chunk's pixels (latency hidden by produce)
        float rr = 0.f, gg = 0.f, bb = 0.f;
        int pvalid = 0;
        if (tid >= 128 && c + 1 < nch) {
            const int px = start + (c + 1) * KC + (tid - 128);
            if (px < end) {
                pvalid = 1;
                rr = R[px]; gg = R[NPIX + px]; bb = R[2 * NPIX + px];
            }
        }

        // ---- produce operand panels (2 passes: pairs p2, p2+16) ----
#pragma unroll
        for (int pass = 0; pass < 2; ++pass) {
            const int pr = p2 + 16 * pass;
            const float4 Pa = spix[buf][2 * pr];
            const float4 Pb = spix[buf][2 * pr + 1];
            const float da = (vec == 0) ? Pa.x : ((vec == 1) ? Pa.y : Pa.z);
            const float db = (vec == 0) ? Pb.x : ((vec == 1) ? Pb.y : Pb.z);
            const __half2 iy2 = __floats2half2_rn(Pa.w, Pb.w);
            uint32_t* selA = A + pr * LDA;
            uint32_t* selB = ((vec == 1) ? B0 : B1) + pr * LDB;
#pragma unroll
            for (int j = 0; j < 16; ++j) {
                const int bin = t2 + 4 * ((j + rot) & 15);
                const float negd = fmaf((float)bin, -QSTEP, 150.0f);
                const float qa = fmaf(da, 50.f, negd);
                const float qb = fmaf(db, 50.f, negd);
                const float dena = fmaf(qa, qa, 1.f);
                const float denb = fmaf(qb, qb, 1.f);
                // den>65504 -> inf -> rcp=0 (tail k<1.5e-5 dropped; harmless)
                const __half2 k2 = h2rcp(__floats2half2_rn(dena, denb));
                if (vec == 0) {
                    __half2 v = __hmul2(iy2, k2);
                    selA[bin] = *(const uint32_t*)&v;
                } else if (vec == 1) {
                    selB[bin] = *(const uint32_t*)&k2;
                    __half2 v = __hmul2(iy2, k2);
                    selA[64 + bin] = *(const uint32_t*)&v;
                } else {
                    selB[bin] = *(const uint32_t*)&k2;
                }
            }
        }

        // finish pixel prep for next chunk into the other spix buffer
        if (tid >= 128 && c + 1 < nch) {
            float4 P = make_float4(0.f, 0.f, 0.f, 0.f);
            if (pvalid) P = pix_math(rr, gg, bb);
            spix[buf ^ 1][tid - 128] = P;
        }
        __syncthreads();

        // ---- MMA: 4 k16 steps, 32 tiles per warp (no trailing sync) ----
        const uint32_t* Bp = (m == 0) ? B0 : B1;
#pragma unroll
        for (int ks = 0; ks < 4; ++ks) {
            const int r0 = (ks * 8 + kc) * LDA + rowbase;
            const int r1 = r0 + 4 * LDA;
            const uint32_t a00 = A[r0],      a01 = A[r0 + 8];
            const uint32_t a02 = A[r1],      a03 = A[r1 + 8];
            const uint32_t a10 = A[r0 + 16], a11 = A[r0 + 24];
            const uint32_t a12 = A[r1 + 16], a13 = A[r1 + 24];
            const int bb0 = (ks * 8 + kc) * LDB + ln4;
            const int bb1 = bb0 + 4 * LDB;
#pragma unroll
            for (int t = 0; t < 8; ++t) {
                const uint32_t b0 = Bp[bb0 + 8 * t];
                const uint32_t b1 = Bp[bb1 + 8 * t];
                mma16(acc[0][t], a00, a01, a02, a03, b0, b1);
                mma16(acc[1][t], a10, a11, a12, a13, b0, b1);
            }
        }
    }

    // ---- per-batch mass for normalization ----
    float lsum = 0.f;
#pragma unroll
    for (int s = 0; s < 2; ++s)
#pragma unroll
        for (int t = 0; t < 8; ++t)
#pragma unroll
            for (int i = 0; i < 4; ++i) lsum += acc[s][t][i];
#pragma unroll
    for (int o = 16; o > 0; o >>= 1) lsum += __shfl_xor_sync(~0u, lsum, o);
    if (lane == 0) atomicAdd(&g_sum[b], lsum);

    // ---- flush partial G ----
    float* Gm = g_G + (size_t)b * 3 * 4096 + m * 4096;
    const int urow = 32 * rh + ln4;
    const int col  = 2 * (lane & 3);
#pragma unroll
    for (int s = 0; s < 2; ++s) {
#pragma unroll
        for (int t = 0; t < 8; ++t) {
            float* p0 = Gm + (urow + 16 * s) * 64 + 8 * t + col;
            atomicAdd(p0,              acc[s][t][0]);
            atomicAdd(p0 + 1,          acc[s][t][1]);
            atomicAdd(p0 + 8 * 64,     acc[s][t][2]);
            atomicAdd(p0 + 8 * 64 + 1, acc[s][t][3]);
        }
    }
}

// ---- Hellinger partial sums: 24 CTAs (batch x matrix); also re-zero g_G ----
__global__ void hell_kernel(const float* __restrict__ th) {
    __shared__ float sh[8];
    const int bc = blockIdx.x;
    const int b  = bc / 3, c = bc % 3;
    const float inv = 1.0f / (g_sum[b] + EPSV);
    float* Gb = g_G + (size_t)b * 3 * 4096 + c * 4096;

    float a = 0.f;
    for (int i = threadIdx.x; i < 4096; i += 256) {
        const int u = i >> 6, v = i & 63;
        int addr;
        if (c == 0)      addr = i;
        else if (c == 1) addr = ((63 - u) << 6) + v;
        else             addr = ((63 - u) << 6) + (63 - v);
        const float h = Gb[addr] * inv;
        Gb[addr] = 0.f;                       // reset for next graph replay
        const float d = sqrtf(th[c * 4096 + i]) - sqrtf(h);
        a = fmaf(d, d, a);
    }
#pragma unroll
    for (int o = 16; o > 0; o >>= 1) a += __shfl_xor_sync(~0u, a, o);
    if ((threadIdx.x & 31) == 0) sh[threadIdx.x >> 5] = a;
    __syncthreads();
    if (threadIdx.x == 0) {
        float s = 0.f;
#pragma unroll
        for (int i = 0; i < 8; ++i) s += sh[i];
        atomicAdd(&g_acc, s);
    }
}

__global__ void final_kernel(float* __restrict__ out, int B) {
    out[0] = sqrtf(g_acc) * (0.70710678118654752f / (float)B);
    g_acc = 0.f;
#pragma unroll
    for (int i = 0; i < 8; ++i) g_sum[i] = 0.f;
}

extern "C" void kernel_launch(void* const* d_in, const int* in_sizes, int n_in,
                              void* d_out, int out_size) {
    const float* rgbd = (const float*)d_in[0];
    const float* th   = (const float*)d_in[1];
    float* out        = (float*)d_out;

    const int B = in_sizes[0] / (4 * NPIX);   // 8

    cudaFuncSetAttribute(hist_kernel,
                         cudaFuncAttributeMaxDynamicSharedMemorySize, DSMEMB);
    hist_kernel<<<B * PARTS, 192, DSMEMB>>>(rgbd);
    hell_kernel<<<B * 3, 256>>>(th);
    final_kernel<<<1, 1>>>(out, B);
}

// round 6
// speedup vs baseline: 4.1688x; 1.1666x over previous
#include <cuda_runtime.h>
#include <cuda_fp16.h>
#include <cstdint>

// HistoGAN histogram loss via mma.sync f16 + ldmatrix, K-contiguous swizzled
// operands, KC=64, double-buffered stages, one sync per chunk, f32 MUFU rcp
// (random-rounding f16 pack -> errors cancel over the 65K-pixel sum).
//
// A-stack (128 rows, K=px): rows 0-63 = Iy*k01, rows 64-127 = Iy*k02
// B0 = k02 (64 cols), B1 = k12 (64 cols).
//   G_AB = Atop x B0, G_AC = Atop x B1, G_BC = Abot x B1
// hist0[u,v]=G_AB[u,v]; hist1[u,v]=G_AC[63-u,v]; hist2[u,v]=G_BC[63-u,63-v]
//
// SMEM operand layout: row-major, 64 f16 per row (=128B), 16B-block swizzle
// blk' = blk ^ (row & 7). Producer STS.128 conflict-free; consumer ldmatrix.x4.

#define EPSV  (6.4f / 255.0f)
#define NPIX  65536
#define PARTS 37
#define QSTEP 4.761904761904762f   /* 300/63 */
#define KC    64

#define A_OFF   0
#define B0_OFF  16384
#define B1_OFF  24576
#define STAGEB  32768
#define DSMEMB  (2 * STAGEB)

__device__ float g_G[8 * 3 * 4096];   // [B][3][64][64] raw
__device__ float g_sum[8];            // per-batch total mass
__device__ float g_acc;               // Hellinger sum accumulator
__device__ unsigned g_done;           // hell CTA completion counter

static __device__ __forceinline__ float rcpa(float x) {
    float r; asm("rcp.approx.f32 %0, %1;" : "=f"(r) : "f"(x)); return r;
}
static __device__ __forceinline__ uint32_t s2u(const void* p) {
    uint32_t a;
    asm("{ .reg .u64 t; cvta.to.shared.u64 t, %1; cvt.u32.u64 %0, t; }"
        : "=r"(a) : "l"(p));
    return a;
}
static __device__ __forceinline__ uint32_t packh2(float lo, float hi) {
    __half2 h = __floats2half2_rn(lo, hi);
    return *(uint32_t*)&h;
}
static __device__ __forceinline__ void sts128(uint32_t addr, uint32_t w0,
        uint32_t w1, uint32_t w2, uint32_t w3) {
    asm volatile("st.shared.v4.b32 [%0], {%1,%2,%3,%4};"
        :: "r"(addr), "r"(w0), "r"(w1), "r"(w2), "r"(w3));
}
static __device__ __forceinline__ void ldmx4(uint32_t& r0, uint32_t& r1,
        uint32_t& r2, uint32_t& r3, uint32_t addr) {
    asm volatile("ldmatrix.sync.aligned.m8n8.x4.shared.b16 {%0,%1,%2,%3}, [%4];"
        : "=r"(r0), "=r"(r1), "=r"(r2), "=r"(r3) : "r"(addr));
}
static __device__ __forceinline__ void mma16(float* c,
        uint32_t a0, uint32_t a1, uint32_t a2, uint32_t a3,
        uint32_t b0, uint32_t b1) {
    asm("mma.sync.aligned.m16n8k16.row.col.f32.f16.f16.f32 "
        "{%0,%1,%2,%3},{%4,%5,%6,%7},{%8,%9},{%0,%1,%2,%3};"
        : "+f"(c[0]), "+f"(c[1]), "+f"(c[2]), "+f"(c[3])
        : "r"(a0), "r"(a1), "r"(a2), "r"(a3), "r"(b0), "r"(b1));
}

static __device__ __forceinline__ float4 pix_math(float rr, float gg, float bb) {
    float r  = fminf(fmaxf(fmaf(rr, 0.5f, 0.5f), 0.f), 1.f);
    float g  = fminf(fmaxf(fmaf(gg, 0.5f, 0.5f), 0.f), 1.f);
    float bl = fminf(fmaxf(fmaf(bb, 0.5f, 0.5f), 0.f), 1.f);
    float iy = sqrtf(fmaf(r, r, fmaf(g, g, fmaf(bl, bl, EPSV))));
    float lr = __logf(r + EPSV), lg = __logf(g + EPSV), lb = __logf(bl + EPSV);
    return make_float4(lr - lg, lr - lb, lg - lb, iy);
}

__global__ void __launch_bounds__(192, 2)
hist_kernel(const float* __restrict__ rgbd) {
    extern __shared__ char dsm[];                 // 2 operand stages
    __shared__ float sd[2][3][64];                // d01/d02/d12 per pixel, x2
    __shared__ float siy[2][64];                  // Iy per pixel, x2

    const uint32_t smb = s2u(dsm);
    const int tid  = threadIdx.x;
    const int lane = tid & 31;
    const int w    = tid >> 5;
    const int b    = blockIdx.x / PARTS;
    const int part = blockIdx.x % PARTS;
    const int start = (int)((long long)part       * NPIX / PARTS);
    const int end   = (int)((long long)(part + 1) * NPIX / PARTS);
    const float* R  = rgbd + (size_t)b * 4 * NPIX;

    // ---- producer mapping: vec = tid>>6 (0:A-top, 1:B0+A-bot, 2:B1) ----
    const int   vec  = tid >> 6;
    const int   bin  = tid & 63;
    const float negd = 150.0f - (float)bin * QSTEP;
    const int   swp  = bin & 7;
    uint32_t dst1, dst2 = 0;
    if (vec == 0)      { dst1 = A_OFF  + bin * 128; }
    else if (vec == 1) { dst1 = B0_OFF + bin * 128; dst2 = A_OFF + (64 + bin) * 128; }
    else               { dst1 = B1_OFF + bin * 128; }

    // ---- consumer mapping: warp -> matrix m, row-half rh ----
    const int m  = w >> 1;                 // 0=AB, 1=AC, 2=BC
    const int rh = w & 1;
    const int Rb = ((m == 2) ? 64 : 0) + 32 * rh;
    const uint32_t Boff = (m == 0) ? B0_OFF : B1_OFF;
    // A ldmatrix lane geometry (rows fixed per lane)
    const int rowA  = Rb + (lane & 7) + 8 * ((lane >> 3) & 1);
    const int swA   = rowA & 7;
    const int koffA = lane >> 4;                 // 0 or 1 (k-block +8)
    const uint32_t byteA0 = (uint32_t)(A_OFF + rowA * 128);
    const uint32_t byteA1 = byteA0 + 16 * 128;   // rows +16
    // B ldmatrix lane geometry
    const int colB  = (lane & 7) + ((lane >> 1) & 8);   // +8 for lanes 16-31
    const int swB   = lane & 7;
    const int koffB = (lane >> 3) & 1;
    const uint32_t byteBbase = Boff + (uint32_t)colB * 128;

    float acc[2][8][4];
#pragma unroll
    for (int s = 0; s < 2; ++s)
#pragma unroll
        for (int t = 0; t < 8; ++t)
#pragma unroll
            for (int i = 0; i < 4; ++i) acc[s][t][i] = 0.f;

    const int nch = (end - start + KC - 1) / KC;

    // pixel prep for chunk 0 (warps 4,5)
    if (tid >= 128) {
        const int q = tid - 128;
        const int px = start + q;
        float4 P = make_float4(0.f, 0.f, 0.f, 0.f);
        if (px < end) P = pix_math(R[px], R[NPIX + px], R[2 * NPIX + px]);
        sd[0][0][q] = P.x; sd[0][1][q] = P.y; sd[0][2][q] = P.z; siy[0][q] = P.w;
    }
    __syncthreads();

    for (int c = 0; c < nch; ++c) {
        const int buf = c & 1;
        const uint32_t stg = smb + buf * STAGEB;

        // early LDG for next chunk's pixels
        float rr = 0.f, gg = 0.f, bb = 0.f;
        int pvalid = 0;
        if (tid >= 128 && c + 1 < nch) {
            const int px = start + (c + 1) * KC + (tid - 128);
            if (px < end) {
                pvalid = 1;
                rr = R[px]; gg = R[NPIX + px]; bb = R[2 * NPIX + px];
            }
        }

        // ---- produce: 8 blocks of 8 pixels, STS.128 each ----
#pragma unroll
        for (int j = 0; j < 8; ++j) {
            const float4 dA = *(const float4*)&sd[buf][vec][8 * j];
            const float4 dB = *(const float4*)&sd[buf][vec][8 * j + 4];
            float k0 = rcpa(fmaf(fmaf(dA.x, 50.f, negd), fmaf(dA.x, 50.f, negd), 1.f));
            float k1 = rcpa(fmaf(fmaf(dA.y, 50.f, negd), fmaf(dA.y, 50.f, negd), 1.f));
            float k2 = rcpa(fmaf(fmaf(dA.z, 50.f, negd), fmaf(dA.z, 50.f, negd), 1.f));
            float k3 = rcpa(fmaf(fmaf(dA.w, 50.f, negd), fmaf(dA.w, 50.f, negd), 1.f));
            float k4 = rcpa(fmaf(fmaf(dB.x, 50.f, negd), fmaf(dB.x, 50.f, negd), 1.f));
            float k5 = rcpa(fmaf(fmaf(dB.y, 50.f, negd), fmaf(dB.y, 50.f, negd), 1.f));
            float k6 = rcpa(fmaf(fmaf(dB.z, 50.f, negd), fmaf(dB.z, 50.f, negd), 1.f));
            float k7 = rcpa(fmaf(fmaf(dB.w, 50.f, negd), fmaf(dB.w, 50.f, negd), 1.f));
            const uint32_t off = (uint32_t)(((j ^ swp) << 4));
            if (vec == 2) {
                sts128(stg + dst1 + off,
                       packh2(k0, k1), packh2(k2, k3),
                       packh2(k4, k5), packh2(k6, k7));
            } else {
                const float4 iA = *(const float4*)&siy[buf][8 * j];
                const float4 iB = *(const float4*)&siy[buf][8 * j + 4];
                if (vec == 1)   // raw k02 -> B0
                    sts128(stg + dst1 + off,
                           packh2(k0, k1), packh2(k2, k3),
                           packh2(k4, k5), packh2(k6, k7));
                const uint32_t dA2 = (vec == 0) ? (stg + dst1 + off) : (stg + dst2 + off);
                sts128(dA2,
                       packh2(k0 * iA.x, k1 * iA.y), packh2(k2 * iA.z, k3 * iA.w),
                       packh2(k4 * iB.x, k5 * iB.y), packh2(k6 * iB.z, k7 * iB.w));
            }
        }

        // finish pixel prep for next chunk into the other buffers
        if (tid >= 128 && c + 1 < nch) {
            float4 P = make_float4(0.f, 0.f, 0.f, 0.f);
            if (pvalid) P = pix_math(rr, gg, bb);
            const int q = tid - 128;
            sd[buf ^ 1][0][q] = P.x; sd[buf ^ 1][1][q] = P.y;
            sd[buf ^ 1][2][q] = P.z; siy[buf ^ 1][q] = P.w;
        }
        __syncthreads();

        // ---- MMA: 4 k16 steps via ldmatrix.x4 ----
#pragma unroll
        for (int ks = 0; ks < 4; ++ks) {
            uint32_t a0[4], a1[4];
            const uint32_t kxA = (uint32_t)(((2 * ks + koffA) ^ swA) << 4);
            ldmx4(a0[0], a0[1], a0[2], a0[3], stg + byteA0 + kxA);
            ldmx4(a1[0], a1[1], a1[2], a1[3], stg + byteA1 + kxA);
            const uint32_t kxB = (uint32_t)(((2 * ks + koffB) ^ swB) << 4);
#pragma unroll
            for (int j = 0; j < 4; ++j) {
                uint32_t b0a, b1a, b0b, b1b;
                ldmx4(b0a, b1a, b0b, b1b, stg + byteBbase + (uint32_t)(16 * j * 128) + kxB);
                mma16(acc[0][2 * j],     a0[0], a0[1], a0[2], a0[3], b0a, b1a);
                mma16(acc[0][2 * j + 1], a0[0], a0[1], a0[2], a0[3], b0b, b1b);
                mma16(acc[1][2 * j],     a1[0], a1[1], a1[2], a1[3], b0a, b1a);
                mma16(acc[1][2 * j + 1], a1[0], a1[1], a1[2], a1[3], b0b, b1b);
            }
        }
    }

    // ---- per-batch mass for normalization ----
    float lsum = 0.f;
#pragma unroll
    for (int s = 0; s < 2; ++s)
#pragma unroll
        for (int t = 0; t < 8; ++t)
#pragma unroll
            for (int i = 0; i < 4; ++i) lsum += acc[s][t][i];
#pragma unroll
    for (int o = 16; o > 0; o >>= 1) lsum += __shfl_xor_sync(~0u, lsum, o);
    if (lane == 0) atomicAdd(&g_sum[b], lsum);

    // ---- flush partial G ----
    float* Gm = g_G + (size_t)b * 3 * 4096 + m * 4096;
    const int urow = 32 * rh + (lane >> 2);
    const int col  = 2 * (lane & 3);
#pragma unroll
    for (int s = 0; s < 2; ++s) {
#pragma unroll
        for (int t = 0; t < 8; ++t) {
            float* p0 = Gm + (urow + 16 * s) * 64 + 8 * t + col;
            atomicAdd(p0,              acc[s][t][0]);
            atomicAdd(p0 + 1,          acc[s][t][1]);
            atomicAdd(p0 + 8 * 64,     acc[s][t][2]);
            atomicAdd(p0 + 8 * 64 + 1, acc[s][t][3]);
        }
    }
}

// ---- Hellinger: 24 CTAs (batch x matrix); re-zeroes g_G; last CTA finalizes ----
__global__ void hell_kernel(const float* __restrict__ th,
                            float* __restrict__ out, int B) {
    __shared__ float sh[8];
    const int bc = blockIdx.x;
    const int b  = bc / 3, c = bc % 3;
    const float inv = 1.0f / (g_sum[b] + EPSV);
    float* Gb = g_G + (size_t)b * 3 * 4096 + c * 4096;

    float a = 0.f;
    for (int i = threadIdx.x; i < 4096; i += 256) {
        const int u = i >> 6, v = i & 63;
        int addr;
        if (c == 0)      addr = i;
        else if (c == 1) addr = ((63 - u) << 6) + v;
        else             addr = ((63 - u) << 6) + (63 - v);
        const float h = Gb[addr] * inv;
        Gb[addr] = 0.f;                       // reset for next graph replay
        const float d = sqrtf(th[c * 4096 + i]) - sqrtf(h);
        a = fmaf(d, d, a);
    }
#pragma unroll
    for (int o = 16; o > 0; o >>= 1) a += __shfl_xor_sync(~0u, a, o);
    if ((threadIdx.x & 31) == 0) sh[threadIdx.x >> 5] = a;
    __syncthreads();
    if (threadIdx.x == 0) {
        float s = 0.f;
#pragma unroll
        for (int i = 0; i < 8; ++i) s += sh[i];
        atomicAdd(&g_acc, s);
        __threadfence();
        const unsigned rank = atomicAdd(&g_done, 1u);
        if (rank == (unsigned)(3 * B - 1)) {       // last CTA finalizes
            out[0] = sqrtf(g_acc) * (0.70710678118654752f / (float)B);
            g_acc = 0.f;
            g_done = 0u;
#pragma unroll
            for (int i = 0; i < 8; ++i) g_sum[i] = 0.f;
        }
    }
}

extern "C" void kernel_launch(void* const* d_in, const int* in_sizes, int n_in,
                              void* d_out, int out_size) {
    const float* rgbd = (const float*)d_in[0];
    const float* th   = (const float*)d_in[1];
    float* out        = (float*)d_out;

    const int B = in_sizes[0] / (4 * NPIX);   // 8

    cudaFuncSetAttribute(hist_kernel,
                         cudaFuncAttributeMaxDynamicSharedMemorySize, DSMEMB);
    hist_kernel<<<B * PARTS, 192, DSMEMB>>>(rgbd);
    hell_kernel<<<B * 3, 256>>>(th, out, B);
}